// round 16
// baseline (speedup 1.0000x reference)
#include <cuda_runtime.h>
#include <cuda_fp16.h>
#include <cstdint>

#define B_    8
#define CIN   512
#define COUT  512
#define HW    64
#define CKK   4608
#define PLANE 4096
#define EPSV  1e-8f

#define NCHUNK 72            // 8 ci-blocks x 9 kk
#define NT     128           // couts per CTA
#define NTHR   256

// ---- dynamic smem layout (bytes) ----
#define OFF_B    0           // 2 x 16384 (double-buffered B tile: 128 co x 128B)
#define BBUF     16384
#define OFF_AH   32768       // 2 x (264 hp x 64 ci fp16 = 33792) double-buffered A halo
#define AHBUF    33792
#define OFF_INVD 100352      // 128 f32
#define OFF_BIAS 100864      // 128 f32
#define SMEM_SZ  101376

// ---- device scratch ----
__device__ unsigned short g_w16[(size_t)COUT * CKK];   // fp16 normalized W [co][kk*512+ci]
__device__ unsigned short g_xt[(size_t)B_ * PLANE * CIN]; // fp16 modulated x, pixel-major [b][y][x][ci]
__device__ float g_q[COUT * CIN];
__device__ float g_f[B_ * CIN];
__device__ float g_invd[B_ * COUT];

__device__ __forceinline__ uint32_t smem_u32(const void* p) {
    uint32_t a;
    asm("{ .reg .u64 t; cvta.to.shared.u64 t, %1; cvt.u32.u64 %0, t; }" : "=r"(a) : "l"(p));
    return a;
}

#define LDSM4(R, addr)                                                          \
    asm volatile("ldmatrix.sync.aligned.m8n8.x4.shared.b16 {%0,%1,%2,%3}, [%4];"\
        : "=r"((R)[0]), "=r"((R)[1]), "=r"((R)[2]), "=r"((R)[3]) : "r"(addr))
#define MMA16816(D, A, B0, B1)                                                  \
    asm volatile("mma.sync.aligned.m16n8k16.row.col.f32.f16.f16.f32 "           \
        "{%0,%1,%2,%3}, {%4,%5,%6,%7}, {%8,%9}, {%0,%1,%2,%3};"                 \
        : "+f"((D)[0]), "+f"((D)[1]), "+f"((D)[2]), "+f"((D)[3])                \
        : "r"((A)[0]), "r"((A)[1]), "r"((A)[2]), "r"((A)[3]), "r"(B0), "r"(B1))
#define CPA16(dst, src)                                                         \
    asm volatile("cp.async.cg.shared.global [%0], [%1], 16;" :: "r"(dst), "l"(src))
#define CPA16Z(dst, src, sz)                                                    \
    asm volatile("cp.async.cg.shared.global [%0], [%1], 16, %2;" :: "r"(dst), "l"(src), "r"(sz))
#define CPA_COMMIT() asm volatile("cp.async.commit_group;" ::: "memory")
#define CPA_WAIT0()  asm volatile("cp.async.wait_group 0;" ::: "memory")
#define CPA_WAIT1()  asm volatile("cp.async.wait_group 1;" ::: "memory")

// ---------------------------------------------------------------------------
// prep kernels
// ---------------------------------------------------------------------------
__global__ void k_prep_w(const float* __restrict__ weight) {
    const int co = blockIdx.x, tid = threadIdx.x;
    __shared__ float red[8];
    const float* wrow = weight + (size_t)co * CKK;
    float m = 0.0f;
    const float4* w4 = (const float4*)wrow;
    for (int i = tid; i < 1152; i += 256) {
        float4 v = w4[i];
        m = fmaxf(m, fmaxf(fmaxf(fabsf(v.x), fabsf(v.y)), fmaxf(fabsf(v.z), fabsf(v.w))));
    }
#pragma unroll
    for (int o = 16; o; o >>= 1) m = fmaxf(m, __shfl_xor_sync(~0u, m, o));
    if ((tid & 31) == 0) red[tid >> 5] = m;
    __syncthreads();
    m = red[0];
#pragma unroll
    for (int j = 1; j < 8; ++j) m = fmaxf(m, red[j]);

    const float inv = (1.0f / sqrtf((float)CKK)) / m;
    for (int ci = tid; ci < CIN; ci += 256) {
        float qs = 0.0f;
#pragma unroll
        for (int kk = 0; kk < 9; ++kk) {
            float v = wrow[ci * 9 + kk] * inv;
            g_w16[(size_t)co * CKK + kk * 512 + ci] = __half_as_ushort(__float2half_rn(v));
            qs += v * v;
        }
        g_q[co * CIN + ci] = qs;
    }
}

__global__ void k_prep_s(const float* __restrict__ style) {
    const int b = threadIdx.x >> 5, lane = threadIdx.x & 31;
    float m = 0.0f;
#pragma unroll
    for (int t = 0; t < 16; ++t) m = fmaxf(m, fabsf(style[b * CIN + lane + 32 * t]));
#pragma unroll
    for (int o = 16; o; o >>= 1) m = fmaxf(m, __shfl_xor_sync(~0u, m, o));
    const float inv = (1.0f / sqrtf((float)CKK)) / m;
#pragma unroll
    for (int t = 0; t < 16; ++t) {
        int ci = lane + 32 * t;
        g_f[b * CIN + ci] = style[b * CIN + ci] * inv;
    }
}

__global__ void k_demod() {
    const int co = blockIdx.x;
    const int b = threadIdx.x >> 5, lane = threadIdx.x & 31;
    float s = 0.0f;
#pragma unroll
    for (int t = 0; t < 16; ++t) {
        int ci = lane + 32 * t;
        float f = g_f[b * CIN + ci];
        s += f * f * g_q[co * CIN + ci];
    }
#pragma unroll
    for (int o = 16; o; o >>= 1) s += __shfl_xor_sync(~0u, s, o);
    if (lane == 0) g_invd[b * COUT + co] = rsqrtf(s * (float)CKK + EPSV);
}

// transpose + modulate: g_xt[b][y][x][ci] = fp16( x[b][ci][y][x] * f[b][ci] )
// grid (32 y-pairs, 8 cib, 8 b), block 256; 2 rows per block, float4 loads
__global__ void k_xpose(const float* __restrict__ x) {
    __shared__ float ts[2][64][68];
    const int tid = threadIdx.x;
    const int y0 = blockIdx.x * 2, cib = blockIdx.y, b = blockIdx.z;
    const int cig0 = cib * 64;
    {
        const int ci = tid >> 2;            // 0..63
        const int xq = tid & 3;             // float4 group 0..3
        const float fm0 = g_f[b * CIN + cig0 + ci];
        const float4* src = (const float4*)(x + ((size_t)(b * CIN + cig0 + ci) * HW + y0) * HW);
#pragma unroll
        for (int yy = 0; yy < 2; ++yy)
#pragma unroll
            for (int j = 0; j < 4; ++j) {
                float4 v = src[yy * 16 + xq + j * 4];
                int xx = (xq + j * 4) * 4;
                ts[yy][ci][xx]     = v.x * fm0;
                ts[yy][ci][xx + 1] = v.y * fm0;
                ts[yy][ci][xx + 2] = v.z * fm0;
                ts[yy][ci][xx + 3] = v.w * fm0;
            }
    }
    __syncthreads();
    uint32_t* dst = (uint32_t*)g_xt;
#pragma unroll
    for (int it = 0; it < 16; ++it) {
        int idx = tid + it * 256;           // 0..4095
        int yy = idx >> 11;
        int rem = idx & 2047;
        int xx = rem >> 5, cp = rem & 31;
        float v0 = ts[yy][2 * cp][xx], v1 = ts[yy][2 * cp + 1][xx];
        uint32_t h;
        asm("cvt.rn.f16x2.f32 %0, %1, %2;" : "=r"(h) : "f"(v1), "f"(v0));
        dst[(((size_t)b * PLANE + (y0 + yy) * HW + xx) * CIN + cig0) / 2 + cp] = h;
    }
}

// ---------------------------------------------------------------------------
// main conv: fp16 mma.sync implicit GEMM, 8 warps, 2 CTAs/SM  (R12 structure,
// per-chunk address arithmetic hoisted out of the loop)
// ---------------------------------------------------------------------------
__global__ __launch_bounds__(NTHR, 2) void k_conv(
    const float* __restrict__ noise,
    const float* __restrict__ bias,
    const float* __restrict__ nsp,
    float* __restrict__ out)
{
    extern __shared__ char smem[];
    const uint32_t sb = smem_u32(smem);
    const int tid = threadIdx.x;
    const int wid = tid >> 5, lane = tid & 31;
    const int y0 = blockIdx.x * 2;
    const int coBase = blockIdx.y * NT;
    const int b = blockIdx.z;

    float* invd_s = (float*)(smem + OFF_INVD);
    float* bias_s = (float*)(smem + OFF_BIAS);
    if (tid < NT) {
        invd_s[tid] = g_invd[b * COUT + coBase + tid];
        bias_s[tid] = bias[coBase + tid];
    }

    // ---- per-thread invariants: B prefetch ----
    const char* gwB = (const char*)(g_w16 + (size_t)coBase * CKK);
    uint32_t boff[4], bdst[4];
#pragma unroll
    for (int t = 0; t < 4; ++t) {
        int e = tid + t * NTHR;
        int r = e >> 3, u = e & 7;
        boff[t] = (uint32_t)(r * CKK + u * 8) * 2;
        bdst[t] = sb + OFF_B + r * 128 + ((u ^ (r & 7)) << 4);
    }
    // ---- per-thread invariants: A slice ----
    const char* xb = (const char*)g_xt + (size_t)b * PLANE * CIN * 2;
    const int rOff = tid >> 3;
    const uint32_t u8b = (uint32_t)((tid & 7) << 4);

    // ---- group 0: B tile for chunk 0 ----
#pragma unroll
    for (int t = 0; t < 4; ++t) CPA16(bdst[t], gwB + boff[t]);
    CPA_COMMIT();

    // ---- group 1: full A-halo for cib=0 (264 rows x 8 chunks of 16B) ----
    {
#pragma unroll
        for (int it = 0; it < 9; ++it) {
            int e = tid + it * NTHR;
            if (e < 2112) {
                int row = e >> 3, u = e & 7;
                int r = row / 66, cc = row - r * 66;
                int gy = y0 - 1 + r, gx = cc - 1;
                uint32_t ok = ((unsigned)gy < HW && (unsigned)gx < HW) ? 16u : 0u;
                int py = ok ? gy : 0, pxx = ok ? gx : 0;
                const char* src = xb + (size_t)(py * HW + pxx) * CIN * 2 + (u << 4);
                uint32_t dst = sb + OFF_AH + row * 128 + ((u << 4) ^ ((row & 7) << 4));
                CPA16Z(dst, src, ok);
            }
        }
        CPA_COMMIT();
    }

    float acc[64];
#pragma unroll
    for (int i = 0; i < 64; ++i) acc[i] = 0.0f;

    const int wm = wid & 1, wn = wid >> 1;       // warp grid 2(M) x 4(N)
    const int lr = lane & 15, lc = lane >> 4;
    uint32_t bRB[2], kxB[4];
#pragma unroll
    for (int t = 0; t < 2; ++t)
        bRB[t] = sb + OFF_B + (uint32_t)((wn * 32 + t * 16 + lr) * 128);
#pragma unroll
    for (int t = 0; t < 4; ++t)
        kxB[t] = ((uint32_t)(t * 32 + lc * 16)) ^ ((uint32_t)((lr & 7) << 4));

    // ---- per-thread invariants: A LDSM base addresses ----
    int hpb[4];
    uint32_t aBase[4];
#pragma unroll
    for (int t = 0; t < 4; ++t) {
        hpb[t] = wm * 66 + t * 16 + lr;
        aBase[t] = sb + OFF_AH + (uint32_t)(hpb[t] * 128);
    }
    const uint32_t lcx = (uint32_t)(lc << 4);

    for (int c = 0; c < NCHUNK; ++c) {
        const int cib = c / 9;
        const int kk  = c - cib * 9;
        const int dy = kk / 3, dx = kk - dy * 3;

        __syncthreads();                         // MMA[c-1] done (bufs free)

        // ---- issue next prefetch group: B[c+1] + A-slice for block cib+1 ----
        if (c + 1 < NCHUNK) {
            const int c1 = c + 1;
            const int cib1 = c1 / 9, kk1 = c1 - cib1 * 9;
            const uint32_t koff = (uint32_t)(kk1 * 512 + cib1 * 64) * 2;
            const uint32_t bufo = (uint32_t)(c1 & 1) * BBUF;
#pragma unroll
            for (int t = 0; t < 4; ++t)
                CPA16(bdst[t] + bufo, gwB + boff[t] + koff);
        }
        if (cib < 7) {                           // A rows [kk*30, kk*30+nr) of next block
            const int nr = (kk == 8) ? 24 : 30;
            if (rOff < nr) {
                int row = kk * 30 + rOff;
                int r = (row * 993) >> 16;       // /66 for row < 264
                int cc = row - r * 66;
                int gy = y0 - 1 + r, gx = cc - 1;
                uint32_t ok = ((unsigned)gy < HW && (unsigned)gx < HW) ? 16u : 0u;
                int py = ok ? gy : 0, pxx = ok ? gx : 0;
                const char* src = xb + (size_t)(py * HW + pxx) * CIN * 2
                                + (cib + 1) * 128 + u8b;
                uint32_t dst = sb + OFF_AH + (uint32_t)((cib + 1) & 1) * AHBUF
                             + (uint32_t)(row << 7) + (u8b ^ ((row & 7) << 4));
                CPA16Z(dst, src, ok);
            }
        }
        CPA_COMMIT();

        if (c + 1 < NCHUNK) CPA_WAIT1();         // B[c] + A slices arrived (issued last chunk)
        else                CPA_WAIT0();
        __syncthreads();                         // visible to all

        // ---- per-kk shifted A row addresses (from hoisted bases) ----
        const int drow = dy * 66 + dx;
        const uint32_t abo = (uint32_t)(cib & 1) * AHBUF + (uint32_t)(drow << 7);
        uint32_t aAddr[4], aSw[4];
#pragma unroll
        for (int t = 0; t < 4; ++t) {
            aAddr[t] = aBase[t] + abo;
            aSw[t]   = (uint32_t)(((hpb[t] + drow) & 7) << 4);
        }

        // ---- MMA phase: 4 k16 steps ----
        const uint32_t bbo = (uint32_t)(c & 1) * BBUF;
#pragma unroll
        for (int ks = 0; ks < 4; ++ks) {
            uint32_t af[4][4], bf[2][4];
            const uint32_t ko = (uint32_t)(ks << 5);
#pragma unroll
            for (int t = 0; t < 4; ++t) LDSM4(af[t], aAddr[t] + ((ko | lcx) ^ aSw[t]));
#pragma unroll
            for (int t = 0; t < 2; ++t) LDSM4(bf[t], bRB[t] + bbo + kxB[ks]);
#pragma unroll
            for (int tm = 0; tm < 4; ++tm)
#pragma unroll
                for (int tn = 0; tn < 2; ++tn) {
                    MMA16816(acc + (tm * 4 + tn * 2) * 4,     af[tm], bf[tn][0], bf[tn][2]);
                    MMA16816(acc + (tm * 4 + tn * 2 + 1) * 4, af[tm], bf[tn][1], bf[tn][3]);
                }
        }
    }

    // ---- epilogue: direct stores ----
    {
        const float nsv = nsp[0];
        const int y = y0 + wm;
        const float* nrow = noise + (size_t)b * PLANE + y * HW;
        float* orow = out + ((size_t)(b * COUT + coBase)) * PLANE + y * HW;
#pragma unroll
        for (int tm = 0; tm < 4; ++tm)
#pragma unroll
            for (int h = 0; h < 2; ++h) {
                const int px = tm * 16 + (lane >> 2) + 8 * h;
                const float nz = nrow[px] * nsv;
#pragma unroll
                for (int tn4 = 0; tn4 < 4; ++tn4) {
                    const int co = wn * 32 + tn4 * 8 + (lane & 3) * 2;
                    const float d0 = acc[(tm * 4 + tn4) * 4 + 2 * h];
                    const float d1 = acc[(tm * 4 + tn4) * 4 + 2 * h + 1];
                    orow[(size_t)co * PLANE + px]       = d0 * invd_s[co]     + bias_s[co]     + nz;
                    orow[(size_t)(co + 1) * PLANE + px] = d1 * invd_s[co + 1] + bias_s[co + 1] + nz;
                }
            }
    }
}

// ---------------------------------------------------------------------------
extern "C" void kernel_launch(void* const* d_in, const int* in_sizes, int n_in,
                              void* d_out, int out_size) {
    const float* x      = (const float*)d_in[0];
    const float* style  = (const float*)d_in[1];
    const float* noise  = (const float*)d_in[2];
    const float* weight = (const float*)d_in[3];
    const float* bias   = (const float*)d_in[4];
    const float* nsp    = (const float*)d_in[5];
    float* out          = (float*)d_out;

    k_prep_w<<<COUT, 256>>>(weight);
    k_prep_s<<<1, 256>>>(style);
    k_demod<<<COUT, 256>>>();
    {
        dim3 g(32, 8, B_);
        k_xpose<<<g, 256>>>(x);
    }

    cudaFuncSetAttribute(k_conv, cudaFuncAttributeMaxDynamicSharedMemorySize, SMEM_SZ);
    dim3 grid(32, COUT / NT, B_);
    k_conv<<<grid, NTHR, SMEM_SZ>>>(noise, bias, nsp, out);
}

// round 17
// speedup vs baseline: 1.0510x; 1.0510x over previous
#include <cuda_runtime.h>
#include <cuda_fp16.h>
#include <cstdint>

#define B_    8
#define CIN   512
#define COUT  512
#define HW    64
#define CKK   4608
#define PLANE 4096
#define EPSV  1e-8f

#define NCHUNK 72            // 8 ci-blocks x 9 kk
#define NT     128           // couts per CTA
#define NTHR   256

// ---- dynamic smem layout (bytes) ----
#define OFF_B    0           // 2 x 16384 (double-buffered B tile: 128 co x 128B)
#define BBUF     16384
#define OFF_AH   32768       // 2 x (264 hp x 64 ci fp16 = 33792) double-buffered A halo
#define AHBUF    33792
#define OFF_INVD 100352      // 128 f32
#define OFF_BIAS 100864      // 128 f32
#define SMEM_SZ  101376

// ---- device scratch ----
__device__ unsigned short g_w16[(size_t)COUT * CKK];   // fp16 normalized W [co][kk*512+ci]
__device__ unsigned short g_xt[(size_t)B_ * PLANE * CIN]; // fp16 modulated x, pixel-major [b][y][x][ci]
__device__ float g_f[B_ * CIN];
__device__ float g_invd[B_ * COUT];

__device__ __forceinline__ uint32_t smem_u32(const void* p) {
    uint32_t a;
    asm("{ .reg .u64 t; cvta.to.shared.u64 t, %1; cvt.u32.u64 %0, t; }" : "=r"(a) : "l"(p));
    return a;
}

#define LDSM4(R, addr)                                                          \
    asm volatile("ldmatrix.sync.aligned.m8n8.x4.shared.b16 {%0,%1,%2,%3}, [%4];"\
        : "=r"((R)[0]), "=r"((R)[1]), "=r"((R)[2]), "=r"((R)[3]) : "r"(addr))
#define MMA16816(D, A, B0, B1)                                                  \
    asm volatile("mma.sync.aligned.m16n8k16.row.col.f32.f16.f16.f32 "           \
        "{%0,%1,%2,%3}, {%4,%5,%6,%7}, {%8,%9}, {%0,%1,%2,%3};"                 \
        : "+f"((D)[0]), "+f"((D)[1]), "+f"((D)[2]), "+f"((D)[3])                \
        : "r"((A)[0]), "r"((A)[1]), "r"((A)[2]), "r"((A)[3]), "r"(B0), "r"(B1))
#define CPA16(dst, src)                                                         \
    asm volatile("cp.async.cg.shared.global [%0], [%1], 16;" :: "r"(dst), "l"(src))
#define CPA16Z(dst, src, sz)                                                    \
    asm volatile("cp.async.cg.shared.global [%0], [%1], 16, %2;" :: "r"(dst), "l"(src), "r"(sz))
#define CPA_COMMIT() asm volatile("cp.async.commit_group;" ::: "memory")
#define CPA_WAIT0()  asm volatile("cp.async.wait_group 0;" ::: "memory")
#define CPA_WAIT1()  asm volatile("cp.async.wait_group 1;" ::: "memory")

// ---------------------------------------------------------------------------
// prep: per-cout weight inf-norm + fp16 normalized W + fused demod
// ---------------------------------------------------------------------------
__global__ void k_prep_w(const float* __restrict__ weight) {
    const int co = blockIdx.x, tid = threadIdx.x;
    const int wid = tid >> 5, lane = tid & 31;
    __shared__ float red[8];
    __shared__ float rsum[8][8];     // [warp][b]
    const float* wrow = weight + (size_t)co * CKK;

    float m = 0.0f;
    const float4* w4 = (const float4*)wrow;
    for (int i = tid; i < 1152; i += 256) {
        float4 v = w4[i];
        m = fmaxf(m, fmaxf(fmaxf(fabsf(v.x), fabsf(v.y)), fmaxf(fabsf(v.z), fabsf(v.w))));
    }
#pragma unroll
    for (int o = 16; o; o >>= 1) m = fmaxf(m, __shfl_xor_sync(~0u, m, o));
    if (lane == 0) red[wid] = m;
    __syncthreads();
    m = red[0];
#pragma unroll
    for (int j = 1; j < 8; ++j) m = fmaxf(m, red[j]);

    const float inv = (1.0f / sqrtf((float)CKK)) / m;
    float part[8];
#pragma unroll
    for (int b = 0; b < 8; ++b) part[b] = 0.0f;

    for (int ci = tid; ci < CIN; ci += 256) {
        float qs = 0.0f;
#pragma unroll
        for (int kk = 0; kk < 9; ++kk) {
            float v = wrow[ci * 9 + kk] * inv;
            g_w16[(size_t)co * CKK + kk * 512 + ci] = __half_as_ushort(__float2half_rn(v));
            qs += v * v;
        }
#pragma unroll
        for (int b = 0; b < 8; ++b) {
            float f = g_f[b * CIN + ci];
            part[b] += f * f * qs;
        }
    }
#pragma unroll
    for (int b = 0; b < 8; ++b) {
#pragma unroll
        for (int o = 16; o; o >>= 1) part[b] += __shfl_xor_sync(~0u, part[b], o);
    }
    if (lane == 0) {
#pragma unroll
        for (int b = 0; b < 8; ++b) rsum[wid][b] = part[b];
    }
    __syncthreads();
    if (tid < 8) {
        float s = 0.0f;
#pragma unroll
        for (int w = 0; w < 8; ++w) s += rsum[w][tid];
        g_invd[tid * COUT + co] = rsqrtf(s * (float)CKK + EPSV);
    }
}

__global__ void k_prep_s(const float* __restrict__ style) {
    const int b = threadIdx.x >> 5, lane = threadIdx.x & 31;
    float m = 0.0f;
#pragma unroll
    for (int t = 0; t < 16; ++t) m = fmaxf(m, fabsf(style[b * CIN + lane + 32 * t]));
#pragma unroll
    for (int o = 16; o; o >>= 1) m = fmaxf(m, __shfl_xor_sync(~0u, m, o));
    const float inv = (1.0f / sqrtf((float)CKK)) / m;
#pragma unroll
    for (int t = 0; t < 16; ++t) {
        int ci = lane + 32 * t;
        g_f[b * CIN + ci] = style[b * CIN + ci] * inv;
    }
}

// transpose + modulate: g_xt[b][y][x][ci] = fp16( x[b][ci][y][x] * f[b][ci] )
// grid (64 y, 8 cib, 8 b), block 256; float4 loads, 16B stores
__global__ void k_xpose(const float* __restrict__ x) {
    __shared__ float ts[64][65];
    const int tid = threadIdx.x;
    const int y = blockIdx.x, cib = blockIdx.y, b = blockIdx.z;
    const int cig0 = cib * 64;
    {
        const int ci = tid >> 2;            // 0..63
        const int xq = tid & 3;             // float4 group 0..3
        const float fm0 = g_f[b * CIN + cig0 + ci];
        const float4* src = (const float4*)(x + ((size_t)(b * CIN + cig0 + ci) * HW + y) * HW);
#pragma unroll
        for (int j = 0; j < 4; ++j) {
            float4 v = src[xq + j * 4];
            int xx = (xq + j * 4) * 4;
            ts[ci][xx]     = v.x * fm0;
            ts[ci][xx + 1] = v.y * fm0;
            ts[ci][xx + 2] = v.z * fm0;
            ts[ci][xx + 3] = v.w * fm0;
        }
    }
    __syncthreads();
    uint4* dst = (uint4*)g_xt;
#pragma unroll
    for (int it = 0; it < 2; ++it) {
        int idx = tid + it * 256;           // 0..511 = (xx, g)
        int g = idx & 7, xx = idx >> 3;
        int c0 = g * 8;
        uint32_t h[4];
#pragma unroll
        for (int p = 0; p < 4; ++p) {
            float v0 = ts[c0 + 2 * p][xx], v1 = ts[c0 + 2 * p + 1][xx];
            asm("cvt.rn.f16x2.f32 %0, %1, %2;" : "=r"(h[p]) : "f"(v1), "f"(v0));
        }
        uint4 vv; vv.x = h[0]; vv.y = h[1]; vv.z = h[2]; vv.w = h[3];
        dst[((size_t)b * PLANE + y * HW + xx) * 64 + cib * 8 + g] = vv;
    }
}

// ---------------------------------------------------------------------------
// main conv: fp16 mma.sync implicit GEMM, 8 warps, 2 CTAs/SM  (R12 structure)
// ---------------------------------------------------------------------------
__global__ __launch_bounds__(NTHR, 2) void k_conv(
    const float* __restrict__ noise,
    const float* __restrict__ bias,
    const float* __restrict__ nsp,
    float* __restrict__ out)
{
    extern __shared__ char smem[];
    const uint32_t sb = smem_u32(smem);
    const int tid = threadIdx.x;
    const int wid = tid >> 5, lane = tid & 31;
    const int y0 = blockIdx.x * 2;
    const int coBase = blockIdx.y * NT;
    const int b = blockIdx.z;

    float* invd_s = (float*)(smem + OFF_INVD);
    float* bias_s = (float*)(smem + OFF_BIAS);
    if (tid < NT) {
        invd_s[tid] = g_invd[b * COUT + coBase + tid];
        bias_s[tid] = bias[coBase + tid];
    }

    // ---- group 0: B tile for chunk 0 ----
    {
        const unsigned short* gsrc = g_w16 + (size_t)coBase * CKK;  // cib=0,kk=0
        const uint32_t Bb = sb + OFF_B;
#pragma unroll
        for (int it = 0; it < 4; ++it) {
            int e = tid + it * NTHR;
            int r = e >> 3, u = e & 7;
            CPA16(Bb + r * 128 + ((u ^ (r & 7)) << 4), gsrc + (size_t)r * CKK + u * 8);
        }
        CPA_COMMIT();
    }
    // ---- group 1: full A-halo for cib=0 (264 rows x 8 chunks of 16B) ----
    {
#pragma unroll
        for (int it = 0; it < 9; ++it) {
            int e = tid + it * NTHR;
            if (e < 2112) {
                int row = e >> 3, u = e & 7;
                int r = row / 66, cc = row - r * 66;
                int gy = y0 - 1 + r, gx = cc - 1;
                uint32_t ok = ((unsigned)gy < HW && (unsigned)gx < HW) ? 16u : 0u;
                int py = ok ? gy : 0, pxx = ok ? gx : 0;
                const char* src = (const char*)(g_xt + ((size_t)b * PLANE + py * HW + pxx) * CIN) + (u << 4);
                uint32_t dst = sb + OFF_AH + row * 128 + ((u << 4) ^ ((row & 7) << 4));
                CPA16Z(dst, src, ok);
            }
        }
        CPA_COMMIT();
    }

    float acc[64];
#pragma unroll
    for (int i = 0; i < 64; ++i) acc[i] = 0.0f;

    const int wm = wid & 1, wn = wid >> 1;       // warp grid 2(M) x 4(N)
    const int lr = lane & 15, lc = lane >> 4;
    uint32_t bRB[2], kxB[4];
#pragma unroll
    for (int t = 0; t < 2; ++t)
        bRB[t] = (uint32_t)((wn * 32 + t * 16 + lr) * 128);
#pragma unroll
    for (int t = 0; t < 4; ++t)
        kxB[t] = ((uint32_t)(t * 32 + lc * 16)) ^ ((uint32_t)((lr & 7) << 4));

    for (int c = 0; c < NCHUNK; ++c) {
        const int cib = c / 9;
        const int kk  = c - cib * 9;
        const int dy = kk / 3, dx = kk - dy * 3;
        const uint32_t ahCur = OFF_AH + (uint32_t)(cib & 1) * AHBUF;

        __syncthreads();                         // MMA[c-1] done (bufs free)

        // ---- issue next prefetch group: B[c+1] + A-slice for block cib+1 ----
        if (c + 1 < NCHUNK) {
            const int c1 = c + 1;
            const int cib1 = c1 / 9, kk1 = c1 - cib1 * 9;
            const unsigned short* gsrc = g_w16 + (size_t)coBase * CKK + kk1 * 512 + cib1 * 64;
            const uint32_t Bb = sb + OFF_B + (c1 & 1) * BBUF;
#pragma unroll
            for (int it = 0; it < 4; ++it) {
                int e = tid + it * NTHR;
                int r = e >> 3, u = e & 7;
                CPA16(Bb + r * 128 + ((u ^ (r & 7)) << 4), gsrc + (size_t)r * CKK + u * 8);
            }
        }
        if (cib < 7) {                           // A rows [kk*30, kk*30+nr) of next block
            const int rBeg = kk * 30;
            const int nr = (kk == 8) ? 24 : 30;
            const int e = tid;
            if (e < nr * 8) {
                int row = rBeg + (e >> 3), u = e & 7;
                int r = row / 66, cc = row - r * 66;
                int gy = y0 - 1 + r, gx = cc - 1;
                uint32_t ok = ((unsigned)gy < HW && (unsigned)gx < HW) ? 16u : 0u;
                int py = ok ? gy : 0, pxx = ok ? gx : 0;
                const char* src = (const char*)(g_xt +
                    ((size_t)b * PLANE + py * HW + pxx) * CIN + (cib + 1) * 64) + (u << 4);
                uint32_t dst = sb + OFF_AH + (uint32_t)((cib + 1) & 1) * AHBUF
                             + row * 128 + ((u << 4) ^ ((row & 7) << 4));
                CPA16Z(dst, src, ok);
            }
        }
        CPA_COMMIT();

        if (c + 1 < NCHUNK) CPA_WAIT1();         // B[c] + A slices arrived (issued last chunk)
        else                CPA_WAIT0();
        __syncthreads();                         // visible to all

        // ---- per-kk shifted A row addresses ----
        uint32_t aAddr[4], aSw[4];
#pragma unroll
        for (int t = 0; t < 4; ++t) {
            int hp = (wm + dy) * 66 + t * 16 + lr + dx;
            aAddr[t] = sb + ahCur + hp * 128;
            aSw[t]   = (uint32_t)((hp & 7) << 4);
        }
        const uint32_t lcx = (uint32_t)(lc << 4);

        // ---- MMA phase: 4 k16 steps ----
        const uint32_t Bb = sb + OFF_B + (c & 1) * BBUF;
#pragma unroll
        for (int ks = 0; ks < 4; ++ks) {
            uint32_t af[4][4], bf[2][4];
            const uint32_t ko = (uint32_t)(ks << 5);
#pragma unroll
            for (int t = 0; t < 4; ++t) LDSM4(af[t], aAddr[t] + ((ko | lcx) ^ aSw[t]));
#pragma unroll
            for (int t = 0; t < 2; ++t) LDSM4(bf[t], Bb + bRB[t] + kxB[ks]);
#pragma unroll
            for (int tm = 0; tm < 4; ++tm)
#pragma unroll
                for (int tn = 0; tn < 2; ++tn) {
                    MMA16816(acc + (tm * 4 + tn * 2) * 4,     af[tm], bf[tn][0], bf[tn][2]);
                    MMA16816(acc + (tm * 4 + tn * 2 + 1) * 4, af[tm], bf[tn][1], bf[tn][3]);
                }
        }
    }

    // ---- epilogue: direct stores ----
    {
        const float nsv = nsp[0];
        const int y = y0 + wm;
        const float* nrow = noise + (size_t)b * PLANE + y * HW;
        float* orow = out + ((size_t)(b * COUT + coBase)) * PLANE + y * HW;
#pragma unroll
        for (int tm = 0; tm < 4; ++tm)
#pragma unroll
            for (int h = 0; h < 2; ++h) {
                const int px = tm * 16 + (lane >> 2) + 8 * h;
                const float nz = nrow[px] * nsv;
#pragma unroll
                for (int tn4 = 0; tn4 < 4; ++tn4) {
                    const int co = wn * 32 + tn4 * 8 + (lane & 3) * 2;
                    const float d0 = acc[(tm * 4 + tn4) * 4 + 2 * h];
                    const float d1 = acc[(tm * 4 + tn4) * 4 + 2 * h + 1];
                    orow[(size_t)co * PLANE + px]       = d0 * invd_s[co]     + bias_s[co]     + nz;
                    orow[(size_t)(co + 1) * PLANE + px] = d1 * invd_s[co + 1] + bias_s[co + 1] + nz;
                }
            }
    }
}

// ---------------------------------------------------------------------------
extern "C" void kernel_launch(void* const* d_in, const int* in_sizes, int n_in,
                              void* d_out, int out_size) {
    const float* x      = (const float*)d_in[0];
    const float* style  = (const float*)d_in[1];
    const float* noise  = (const float*)d_in[2];
    const float* weight = (const float*)d_in[3];
    const float* bias   = (const float*)d_in[4];
    const float* nsp    = (const float*)d_in[5];
    float* out          = (float*)d_out;

    // lazily created on first (uncaptured) call; reused under graph capture
    static cudaStream_t side = nullptr;
    static cudaEvent_t ev1 = nullptr, ev2 = nullptr;
    if (side == nullptr) {
        cudaStreamCreateWithFlags(&side, cudaStreamNonBlocking);
        cudaEventCreateWithFlags(&ev1, cudaEventDisableTiming);
        cudaEventCreateWithFlags(&ev2, cudaEventDisableTiming);
    }

    k_prep_s<<<1, 256>>>(style);
    cudaEventRecord(ev1, 0);
    cudaStreamWaitEvent(side, ev1, 0);
    k_prep_w<<<COUT, 256, 0, side>>>(weight);   // overlapped with k_xpose
    cudaEventRecord(ev2, side);

    {
        dim3 g(64, 8, B_);
        k_xpose<<<g, 256>>>(x);
    }
    cudaStreamWaitEvent(0, ev2, 0);

    cudaFuncSetAttribute(k_conv, cudaFuncAttributeMaxDynamicSharedMemorySize, SMEM_SZ);
    dim3 grid(32, COUT / NT, B_);
    k_conv<<<grid, NTHR, SMEM_SZ>>>(noise, bias, nsp, out);
}